// round 8
// baseline (speedup 1.0000x reference)
#include <cuda_runtime.h>
#include <cuda_bf16.h>
#include <cstdint>
#include <math.h>
#include <float.h>

#define SEQ 4096
#define DMODEL 1280
#define NHEAD 20
#define HDIM 64
#define FFN 5120
#define NSEG 8
#define LN_EPS 1e-5f
#define D3 (3 * DMODEL)

typedef unsigned int u32;

// ---------------------------------------------------------------------------
// Scratch (device globals; no runtime allocation allowed)
// ---------------------------------------------------------------------------
__device__ float g_qkv[SEQ * D3];
__device__ float g_h[SEQ * DMODEL];
__device__ float g_xln[SEQ * DMODEL];
__device__ float g_attn[SEQ * DMODEL];
__device__ float g_yln[SEQ * DMODEL];
__device__ float g_ffn[SEQ * FFN];
__device__ float g_wqkv[DMODEL * D3];
__device__ float g_bqkv[D3];
__device__ float g_wo[DMODEL * DMODEL];
__device__ float g_wf1[DMODEL * FFN];
__device__ float g_wf2[FFN * DMODEL];

// ---------------------------------------------------------------------------
// tf32 round helper
// ---------------------------------------------------------------------------
__device__ __forceinline__ float to_tf32(float x) {
    u32 r;
    asm volatile("cvt.rna.tf32.f32 %0, %1;\n" : "=r"(r) : "f"(x));
    return __uint_as_float(r);
}

// ---------------------------------------------------------------------------
// fp32 -> tf32-rounded fp32 convert (float4 granularity)
// ---------------------------------------------------------------------------
__global__ __launch_bounds__(256) void cvt_kernel(const float* __restrict__ src,
                                                  float* __restrict__ dst, int n4) {
    int i = blockIdx.x * 256 + threadIdx.x;
    if (i < n4) {
        float4 v = *(const float4*)(src + (size_t)i * 4);
        v.x = to_tf32(v.x);
        v.y = to_tf32(v.y);
        v.z = to_tf32(v.z);
        v.w = to_tf32(v.w);
        *(float4*)(dst + (size_t)i * 4) = v;
    }
}

// convert + pack a [R x C] weight into dst with row stride ldd at column off
__global__ __launch_bounds__(256) void cvt_pack_kernel(const float* __restrict__ src,
                                                       float* __restrict__ dst,
                                                       int c4, int n4, int ldd, int off) {
    int i = blockIdx.x * 256 + threadIdx.x;
    if (i < n4) {
        float4 v = *(const float4*)(src + (size_t)i * 4);
        v.x = to_tf32(v.x);
        v.y = to_tf32(v.y);
        v.z = to_tf32(v.z);
        v.w = to_tf32(v.w);
        int row = i / c4;
        int col = (i - row * c4) * 4;
        *(float4*)(dst + (size_t)row * ldd + off + col) = v;
    }
}

// pack QKV bias: [bq | 0 | bv]
__global__ __launch_bounds__(256) void pack_bias_kernel(const float* __restrict__ bq,
                                                        const float* __restrict__ bv,
                                                        float* __restrict__ dst) {
    int i = blockIdx.x * 256 + threadIdx.x;
    if (i < D3) {
        float v = 0.f;
        if (i < DMODEL) v = bq[i];
        else if (i >= 2 * DMODEL) v = bv[i - 2 * DMODEL];
        dst[i] = v;
    }
}

// ---------------------------------------------------------------------------
// LayerNorm -> tf32-rounded fp32 output
// ---------------------------------------------------------------------------
__global__ __launch_bounds__(256) void ln_kernel(const float* __restrict__ x,
                                                 const float* __restrict__ gam,
                                                 const float* __restrict__ bet,
                                                 float* __restrict__ outp) {
    int r = blockIdx.x;
    const float* xr = x + (size_t)r * DMODEL;
    float* outr = outp + (size_t)r * DMODEL;
    int tid = threadIdx.x;

    float s = 0.f, s2 = 0.f;
    for (int i = tid; i < DMODEL; i += 256) {
        float v = xr[i];
        s += v;
        s2 += v * v;
    }
    for (int off = 16; off > 0; off >>= 1) {
        s  += __shfl_xor_sync(0xffffffff, s, off);
        s2 += __shfl_xor_sync(0xffffffff, s2, off);
    }
    __shared__ float ss[8];
    __shared__ float ss2[8];
    int wid = tid >> 5;
    int lane = tid & 31;
    if (lane == 0) { ss[wid] = s; ss2[wid] = s2; }
    __syncthreads();
    if (wid == 0) {
        s  = (lane < 8) ? ss[lane]  : 0.f;
        s2 = (lane < 8) ? ss2[lane] : 0.f;
        for (int off = 4; off > 0; off >>= 1) {
            s  += __shfl_xor_sync(0xffffffff, s, off);
            s2 += __shfl_xor_sync(0xffffffff, s2, off);
        }
        if (lane == 0) { ss[0] = s; ss2[0] = s2; }
    }
    __syncthreads();
    float mu = ss[0] * (1.0f / DMODEL);
    float var = ss2[0] * (1.0f / DMODEL) - mu * mu;
    float inv = rsqrtf(var + LN_EPS);
    for (int i = tid; i < DMODEL; i += 256) {
        float v = (xr[i] - mu) * inv * gam[i] + bet[i];
        outr[i] = to_tf32(v);
    }
}

// ---------------------------------------------------------------------------
// tf32 tensor-core GEMM: C[M,N] = A[M,K] @ B[K,N] (+bias)(+gelu|+res)
// BM=256 BN=128 BK=32, 8 warps (4x2), warp tile 64x64, m16n8k8 tf32 mma.
// Dynamic smem: As 2*256*36 + Bs 2*32*136 floats = 108544 bytes.
// ---------------------------------------------------------------------------
#define EPI_BIAS 0
#define EPI_GELU 1
#define EPI_RES  2

#define APITCH 36
#define BPITCH 136
#define A_STG (256 * APITCH)
#define B_STG (32 * BPITCH)
#define TG_SMEM ((2 * A_STG + 2 * B_STG) * 4)

__device__ __forceinline__ void mma_tf32(float* c, u32 a0, u32 a1, u32 a2, u32 a3,
                                         u32 b0, u32 b1) {
    asm volatile(
        "mma.sync.aligned.m16n8k8.row.col.f32.tf32.tf32.f32 "
        "{%0,%1,%2,%3},{%4,%5,%6,%7},{%8,%9},{%0,%1,%2,%3};\n"
        : "+f"(c[0]), "+f"(c[1]), "+f"(c[2]), "+f"(c[3])
        : "r"(a0), "r"(a1), "r"(a2), "r"(a3), "r"(b0), "r"(b1));
}
__device__ __forceinline__ void cp_async16(u32 dst, const void* src) {
    asm volatile("cp.async.cg.shared.global [%0],[%1],16;\n" :: "r"(dst), "l"(src));
}
__device__ __forceinline__ void cp_commit() {
    asm volatile("cp.async.commit_group;\n");
}
__device__ __forceinline__ void cp_wait1() {
    asm volatile("cp.async.wait_group 1;\n");
}
__device__ __forceinline__ void cp_wait0() {
    asm volatile("cp.async.wait_group 0;\n");
}

__device__ __forceinline__ void sg_load_tile(
    const float* A, const float* B, float* As_s, float* Bs_s,
    int k0, int bm, int bn, int K, int N,
    int a_ld_row, int a_ld_col, int b_ld_row, int b_ld_col) {
#pragma unroll
    for (int it = 0; it < 8; it++) {
        int r = a_ld_row + it * 32;
        u32 d = (u32)__cvta_generic_to_shared(As_s + r * APITCH + a_ld_col);
        cp_async16(d, A + (size_t)(bm * 256 + r) * K + k0 + a_ld_col);
    }
#pragma unroll
    for (int it = 0; it < 4; it++) {
        int r = b_ld_row + it * 8;
        u32 d = (u32)__cvta_generic_to_shared(Bs_s + r * BPITCH + b_ld_col);
        cp_async16(d, B + (size_t)(k0 + r) * N + bn * 128 + b_ld_col);
    }
}

template <int EPI, int OUTRND>
__global__ __launch_bounds__(256) void tgemm_kernel(
    const float* __restrict__ A, const float* __restrict__ B,
    const float* __restrict__ bias, const float* __restrict__ res,
    float* __restrict__ C, int M, int N, int K) {
    extern __shared__ float smbuf[];
    float* As = smbuf;                 // 2 stages of 256 x APITCH
    float* Bs = smbuf + 2 * A_STG;     // 2 stages of 32 x BPITCH

    int tid = threadIdx.x;
    int bm = blockIdx.y;
    int bn = blockIdx.x;
    int lane = tid & 31;
    int warp = tid >> 5;
    int wm = warp >> 1;      // 0..3 -> 64-row tile
    int wn = warp & 1;       // 0..1 -> 64-col tile

    int a_ld_row = tid >> 3;        // 0..31
    int a_ld_col = (tid & 7) * 4;   // 0..28
    int b_ld_row = tid >> 5;        // 0..7
    int b_ld_col = (tid & 31) * 4;  // 0..124

    float acc[4][8][4];
#pragma unroll
    for (int mi = 0; mi < 4; mi++) {
#pragma unroll
        for (int nj = 0; nj < 8; nj++) {
#pragma unroll
            for (int e = 0; e < 4; e++) acc[mi][nj][e] = 0.f;
        }
    }

    int KT = K / 32;

    sg_load_tile(A, B, As, Bs, 0, bm, bn, K, N,
                 a_ld_row, a_ld_col, b_ld_row, b_ld_col);
    cp_commit();

    int gID = lane >> 2;
    int tig = lane & 3;

    for (int kt = 0; kt < KT; kt++) {
        int s = kt & 1;
        if (kt + 1 < KT) {
            int s2 = s ^ 1;
            sg_load_tile(A, B, As + s2 * A_STG, Bs + s2 * B_STG,
                         (kt + 1) * 32, bm, bn, K, N,
                         a_ld_row, a_ld_col, b_ld_row, b_ld_col);
            cp_commit();
            cp_wait1();
        } else {
            cp_wait0();
        }
        __syncthreads();

        float* As_s = As + s * A_STG;
        float* Bs_s = Bs + s * B_STG;

#pragma unroll
        for (int kk = 0; kk < 4; kk++) {
            int k0 = kk * 8;
            u32 a_frag[4][4];
#pragma unroll
            for (int mi = 0; mi < 4; mi++) {
                int r0 = wm * 64 + mi * 16;
                a_frag[mi][0] = __float_as_uint(As_s[(r0 + gID) * APITCH + k0 + tig]);
                a_frag[mi][1] = __float_as_uint(As_s[(r0 + 8 + gID) * APITCH + k0 + tig]);
                a_frag[mi][2] = __float_as_uint(As_s[(r0 + gID) * APITCH + k0 + 4 + tig]);
                a_frag[mi][3] = __float_as_uint(As_s[(r0 + 8 + gID) * APITCH + k0 + 4 + tig]);
            }
#pragma unroll
            for (int nj = 0; nj < 8; nj++) {
                int n0 = wn * 64 + nj * 8;
                u32 b0 = __float_as_uint(Bs_s[(k0 + tig) * BPITCH + n0 + gID]);
                u32 b1 = __float_as_uint(Bs_s[(k0 + 4 + tig) * BPITCH + n0 + gID]);
#pragma unroll
                for (int mi = 0; mi < 4; mi++) {
                    mma_tf32(acc[mi][nj], a_frag[mi][0], a_frag[mi][1],
                             a_frag[mi][2], a_frag[mi][3], b0, b1);
                }
            }
        }
        __syncthreads();
    }

#pragma unroll
    for (int mi = 0; mi < 4; mi++) {
        int row0 = bm * 256 + wm * 64 + mi * 16 + gID;
#pragma unroll
        for (int nj = 0; nj < 8; nj++) {
            int col = bn * 128 + wn * 64 + nj * 8 + tig * 2;
            float v0 = acc[mi][nj][0];
            float v1 = acc[mi][nj][1];
            float v2 = acc[mi][nj][2];
            float v3 = acc[mi][nj][3];
            if (bias != 0) {
                float b0 = bias[col];
                float b1 = bias[col + 1];
                v0 += b0; v1 += b1; v2 += b0; v3 += b1;
            }
            if (EPI == EPI_GELU) {
                v0 = 0.5f * v0 * (1.0f + erff(v0 * 0.70710678118654752f));
                v1 = 0.5f * v1 * (1.0f + erff(v1 * 0.70710678118654752f));
                v2 = 0.5f * v2 * (1.0f + erff(v2 * 0.70710678118654752f));
                v3 = 0.5f * v3 * (1.0f + erff(v3 * 0.70710678118654752f));
            }
            if (EPI == EPI_RES) {
                v0 += res[(size_t)row0 * N + col];
                v1 += res[(size_t)row0 * N + col + 1];
                v2 += res[(size_t)(row0 + 8) * N + col];
                v3 += res[(size_t)(row0 + 8) * N + col + 1];
            }
            if (OUTRND) {
                v0 = to_tf32(v0);
                v1 = to_tf32(v1);
                v2 = to_tf32(v2);
                v3 = to_tf32(v3);
            }
            C[(size_t)row0 * N + col] = v0;
            C[(size_t)row0 * N + col + 1] = v1;
            C[(size_t)(row0 + 8) * N + col] = v2;
            C[(size_t)(row0 + 8) * N + col + 1] = v3;
        }
    }
}

// ---------------------------------------------------------------------------
// Block-diagonal attention, tensor-core tf32. q/k/v have row stride ldqkv.
// ---------------------------------------------------------------------------
#define SPITCH 516
#define QPITCH 68
#define KVPITCH_K 73
#define KVPITCH_V 72
#define ATT_SMEM_FLOATS (64 * SPITCH + 64 * QPITCH + 64 * KVPITCH_K)

__global__ __launch_bounds__(256) void attn_kernel(
    const float* __restrict__ q, const float* __restrict__ k,
    const float* __restrict__ v, const int* __restrict__ cu,
    float* __restrict__ outp, int ldqkv) {
    extern __shared__ float sm[];
    float* sc  = sm;
    float* Qs  = sm + 64 * SPITCH;
    float* KVs = Qs + 64 * QPITCH;

    int h = blockIdx.y;
    int q0 = blockIdx.x * 64;

    int g = 0;
    for (int i = 0; i < NSEG; i++) {
        if (cu[i] <= q0) g = i;
    }
    int s0 = cu[g];
    int s1 = cu[g + 1];
    int len = s1 - s0;
    if (len > 512) len = 512;
    int nchunks = (len + 63) >> 6;

    int tid = threadIdx.x;
    int lane = tid & 31;
    int warp = tid >> 5;
    int wm = warp >> 1;
    int wn = warp & 1;
    int gID = lane >> 2;
    int tig = lane & 3;
    const float scale = 0.125f;

#pragma unroll
    for (int t = 0; t < 4; t++) {
        int gi = tid + t * 256;
        int i = gi >> 4;
        int d4 = (gi & 15) * 4;
        float4 qv = *(const float4*)(q + (size_t)(q0 + i) * ldqkv + h * HDIM + d4);
        *(float4*)(Qs + i * QPITCH + d4) = qv;
    }
    __syncthreads();

    int m0 = wm * 16;
    u32 qa[8][4];
#pragma unroll
    for (int ks = 0; ks < 8; ks++) {
        int k0 = ks * 8;
        qa[ks][0] = __float_as_uint(Qs[(m0 + gID) * QPITCH + k0 + tig]);
        qa[ks][1] = __float_as_uint(Qs[(m0 + 8 + gID) * QPITCH + k0 + tig]);
        qa[ks][2] = __float_as_uint(Qs[(m0 + gID) * QPITCH + k0 + 4 + tig]);
        qa[ks][3] = __float_as_uint(Qs[(m0 + 8 + gID) * QPITCH + k0 + 4 + tig]);
    }

    for (int c = 0; c < nchunks; c++) {
        __syncthreads();
#pragma unroll
        for (int t = 0; t < 4; t++) {
            int gi = tid + t * 256;
            int j = gi >> 4;
            int d4 = (gi & 15) * 4;
            int krow = s0 + c * 64 + j;
            float4 kv = make_float4(0.f, 0.f, 0.f, 0.f);
            if (krow < s1) {
                kv = *(const float4*)(k + (size_t)krow * ldqkv + h * HDIM + d4);
            }
            KVs[(d4 + 0) * KVPITCH_K + j] = kv.x;
            KVs[(d4 + 1) * KVPITCH_K + j] = kv.y;
            KVs[(d4 + 2) * KVPITCH_K + j] = kv.z;
            KVs[(d4 + 3) * KVPITCH_K + j] = kv.w;
        }
        __syncthreads();

        float acc[4][4];
#pragma unroll
        for (int nt = 0; nt < 4; nt++) {
#pragma unroll
            for (int e = 0; e < 4; e++) acc[nt][e] = 0.f;
        }
#pragma unroll
        for (int ks = 0; ks < 8; ks++) {
            int k0 = ks * 8;
#pragma unroll
            for (int nt = 0; nt < 4; nt++) {
                int n0 = wn * 32 + nt * 8;
                u32 b0 = __float_as_uint(KVs[(k0 + tig) * KVPITCH_K + n0 + gID]);
                u32 b1 = __float_as_uint(KVs[(k0 + 4 + tig) * KVPITCH_K + n0 + gID]);
                mma_tf32(acc[nt], qa[ks][0], qa[ks][1], qa[ks][2], qa[ks][3], b0, b1);
            }
        }
        int row0 = m0 + gID;
#pragma unroll
        for (int nt = 0; nt < 4; nt++) {
            int col = c * 64 + wn * 32 + nt * 8 + tig * 2;
            sc[row0 * SPITCH + col]           = acc[nt][0] * scale;
            sc[row0 * SPITCH + col + 1]       = acc[nt][1] * scale;
            sc[(row0 + 8) * SPITCH + col]     = acc[nt][2] * scale;
            sc[(row0 + 8) * SPITCH + col + 1] = acc[nt][3] * scale;
        }
    }
    __syncthreads();

    for (int r = warp; r < 64; r += 8) {
        float* row = sc + r * SPITCH;
        float m = -FLT_MAX;
        for (int j = lane; j < len; j += 32) m = fmaxf(m, row[j]);
        for (int off = 16; off > 0; off >>= 1) {
            m = fmaxf(m, __shfl_xor_sync(0xffffffff, m, off));
        }
        float s = 0.f;
        for (int j = lane; j < len; j += 32) {
            float e = __expf(row[j] - m);
            row[j] = e;
            s += e;
        }
        for (int off = 16; off > 0; off >>= 1) {
            s += __shfl_xor_sync(0xffffffff, s, off);
        }
        float inv = 1.0f / s;
        for (int j = lane; j < len; j += 32) row[j] = to_tf32(row[j] * inv);
    }
    __syncthreads();

    float acco[4][4];
#pragma unroll
    for (int nt = 0; nt < 4; nt++) {
#pragma unroll
        for (int e = 0; e < 4; e++) acco[nt][e] = 0.f;
    }

    for (int c = 0; c < nchunks; c++) {
        __syncthreads();
#pragma unroll
        for (int t = 0; t < 4; t++) {
            int gi = tid + t * 256;
            int j = gi >> 4;
            int d4 = (gi & 15) * 4;
            int vrow = s0 + c * 64 + j;
            float4 vv = make_float4(0.f, 0.f, 0.f, 0.f);
            if (vrow < s1) {
                vv = *(const float4*)(v + (size_t)vrow * ldqkv + h * HDIM + d4);
            }
            *(float4*)(KVs + j * KVPITCH_V + d4) = vv;
        }
        __syncthreads();

#pragma unroll
        for (int ks = 0; ks < 8; ks++) {
            int kg = c * 64 + ks * 8;
            int kl = ks * 8;
            u32 pa0 = __float_as_uint(sc[(m0 + gID) * SPITCH + kg + tig]);
            u32 pa1 = __float_as_uint(sc[(m0 + 8 + gID) * SPITCH + kg + tig]);
            u32 pa2 = __float_as_uint(sc[(m0 + gID) * SPITCH + kg + 4 + tig]);
            u32 pa3 = __float_as_uint(sc[(m0 + 8 + gID) * SPITCH + kg + 4 + tig]);
#pragma unroll
            for (int nt = 0; nt < 4; nt++) {
                int n0 = wn * 32 + nt * 8;
                u32 b0 = __float_as_uint(KVs[(kl + tig) * KVPITCH_V + n0 + gID]);
                u32 b1 = __float_as_uint(KVs[(kl + 4 + tig) * KVPITCH_V + n0 + gID]);
                mma_tf32(acco[nt], pa0, pa1, pa2, pa3, b0, b1);
            }
        }
    }

    int orow0 = q0 + m0 + gID;
#pragma unroll
    for (int nt = 0; nt < 4; nt++) {
        int col = h * HDIM + wn * 32 + nt * 8 + tig * 2;
        outp[(size_t)orow0 * DMODEL + col]           = to_tf32(acco[nt][0]);
        outp[(size_t)orow0 * DMODEL + col + 1]       = to_tf32(acco[nt][1]);
        outp[(size_t)(orow0 + 8) * DMODEL + col]     = to_tf32(acco[nt][2]);
        outp[(size_t)(orow0 + 8) * DMODEL + col + 1] = to_tf32(acco[nt][3]);
    }
}

// ---------------------------------------------------------------------------
// launch
// ---------------------------------------------------------------------------
extern "C" void kernel_launch(void* const* d_in, const int* in_sizes, int n_in,
                              void* d_out, int out_size) {
    const float* hidden = (const float*)d_in[0];
    const int*   cu     = (const int*)d_in[1];
    const float* Wq = (const float*)d_in[2];
    const float* bq = (const float*)d_in[3];
    const float* Wk = (const float*)d_in[4];
    const float* Wv = (const float*)d_in[5];
    const float* bv = (const float*)d_in[6];
    const float* Wo = (const float*)d_in[7];
    const float* bo = (const float*)d_in[8];
    const float* ln1_g = (const float*)d_in[9];
    const float* ln1_b = (const float*)d_in[10];
    const float* Wf1 = (const float*)d_in[11];
    const float* bf1 = (const float*)d_in[12];
    const float* Wf2 = (const float*)d_in[13];
    const float* bf2 = (const float*)d_in[14];
    const float* ln2_g = (const float*)d_in[15];
    const float* ln2_b = (const float*)d_in[16];
    float* out = (float*)d_out;

    float *qkvp, *hp, *xlnp, *attnp, *ylnp, *ffnp;
    float *wqkvp, *bqkvp, *wop, *wf1p, *wf2p;
    cudaGetSymbolAddress((void**)&qkvp,  g_qkv);
    cudaGetSymbolAddress((void**)&hp,    g_h);
    cudaGetSymbolAddress((void**)&xlnp,  g_xln);
    cudaGetSymbolAddress((void**)&attnp, g_attn);
    cudaGetSymbolAddress((void**)&ylnp,  g_yln);
    cudaGetSymbolAddress((void**)&ffnp,  g_ffn);
    cudaGetSymbolAddress((void**)&wqkvp, g_wqkv);
    cudaGetSymbolAddress((void**)&bqkvp, g_bqkv);
    cudaGetSymbolAddress((void**)&wop,   g_wo);
    cudaGetSymbolAddress((void**)&wf1p,  g_wf1);
    cudaGetSymbolAddress((void**)&wf2p,  g_wf2);

    static bool attr_set = false;
    if (!attr_set) {
        cudaFuncSetAttribute(attn_kernel, cudaFuncAttributeMaxDynamicSharedMemorySize,
                             ATT_SMEM_FLOATS * (int)sizeof(float));
        cudaFuncSetAttribute(tgemm_kernel<EPI_BIAS, 1>,
                             cudaFuncAttributeMaxDynamicSharedMemorySize, TG_SMEM);
        cudaFuncSetAttribute(tgemm_kernel<EPI_RES, 0>,
                             cudaFuncAttributeMaxDynamicSharedMemorySize, TG_SMEM);
        cudaFuncSetAttribute(tgemm_kernel<EPI_GELU, 1>,
                             cudaFuncAttributeMaxDynamicSharedMemorySize, TG_SMEM);
        attr_set = true;
    }

    dim3 blk(256);
    int nDD4 = DMODEL * DMODEL / 4;
    int nDF4 = DMODEL * FFN / 4;
    int c4 = DMODEL / 4;
    // pack Q/K/V weights into one [DMODEL x 3*DMODEL] matrix (tf32-rounded)
    cvt_pack_kernel<<<(nDD4 + 255) / 256, blk>>>(Wq, wqkvp, c4, nDD4, D3, 0);
    cvt_pack_kernel<<<(nDD4 + 255) / 256, blk>>>(Wk, wqkvp, c4, nDD4, D3, DMODEL);
    cvt_pack_kernel<<<(nDD4 + 255) / 256, blk>>>(Wv, wqkvp, c4, nDD4, D3, 2 * DMODEL);
    pack_bias_kernel<<<(D3 + 255) / 256, blk>>>(bq, bv, bqkvp);
    cvt_kernel<<<(nDD4 + 255) / 256, blk>>>(Wo,  wop,  nDD4);
    cvt_kernel<<<(nDF4 + 255) / 256, blk>>>(Wf1, wf1p, nDF4);
    cvt_kernel<<<(nDF4 + 255) / 256, blk>>>(Wf2, wf2p, nDF4);

    dim3 gemmQKV(D3 / 128, SEQ / 256);
    dim3 gemmDD(DMODEL / 128, SEQ / 256);
    dim3 gemmDF(FFN / 128, SEQ / 256);

    ln_kernel<<<SEQ, blk>>>(hidden, ln1_g, ln1_b, xlnp);
    // fused QKV (tf32-rounded outputs, attention mma operands)
    tgemm_kernel<EPI_BIAS, 1><<<gemmQKV, blk, TG_SMEM>>>(
        xlnp, wqkvp, bqkvp, 0, qkvp, SEQ, D3, DMODEL);
    attn_kernel<<<dim3(SEQ / 64, NHEAD), blk, ATT_SMEM_FLOATS * sizeof(float)>>>(
        qkvp, qkvp + DMODEL, qkvp + 2 * DMODEL, cu, attnp, D3);
    tgemm_kernel<EPI_RES, 0><<<gemmDD, blk, TG_SMEM>>>(
        attnp, wop, bo, hidden, hp, SEQ, DMODEL, DMODEL);
    ln_kernel<<<SEQ, blk>>>(hp, ln2_g, ln2_b, ylnp);
    tgemm_kernel<EPI_GELU, 1><<<gemmDF, blk, TG_SMEM>>>(
        ylnp, wf1p, bf1, 0, ffnp, SEQ, FFN, DMODEL);
    tgemm_kernel<EPI_RES, 0><<<gemmDD, blk, TG_SMEM>>>(
        ffnp, wf2p, bf2, hp, out, SEQ, DMODEL, FFN);
}

// round 9
// speedup vs baseline: 1.7501x; 1.7501x over previous
#include <cuda_runtime.h>
#include <cuda_fp16.h>
#include <cstdint>
#include <math.h>
#include <float.h>

#define SEQ 4096
#define DMODEL 1280
#define NHEAD 20
#define HDIM 64
#define FFN 5120
#define NSEG 8
#define LN_EPS 1e-5f
#define D3 (3 * DMODEL)

typedef unsigned int u32;
typedef __half f16;

// ---------------------------------------------------------------------------
// Scratch (device globals; no runtime allocation allowed)
// ---------------------------------------------------------------------------
__device__ float g_qkv[SEQ * D3];          // tf32-rounded fp32 (attention operands)
__device__ float g_h[SEQ * DMODEL];
__device__ f16   g_xln[SEQ * DMODEL];
__device__ f16   g_attn[SEQ * DMODEL];
__device__ f16   g_yln[SEQ * DMODEL];
__device__ f16   g_ffn[SEQ * FFN];
__device__ f16   g_wqkv[DMODEL * D3];
__device__ float g_bqkv[D3];
__device__ f16   g_wo[DMODEL * DMODEL];
__device__ f16   g_wf1[DMODEL * FFN];
__device__ f16   g_wf2[FFN * DMODEL];

// ---------------------------------------------------------------------------
// helpers
// ---------------------------------------------------------------------------
__device__ __forceinline__ float to_tf32(float x) {
    u32 r;
    asm volatile("cvt.rna.tf32.f32 %0, %1;\n" : "=r"(r) : "f"(x));
    return __uint_as_float(r);
}

// fp32 -> fp16 convert (float4 granularity)
__global__ __launch_bounds__(256) void cvt_kernel(const float* __restrict__ src,
                                                  f16* __restrict__ dst, int n4) {
    int i = blockIdx.x * 256 + threadIdx.x;
    if (i < n4) {
        float4 v = *(const float4*)(src + (size_t)i * 4);
        __half2* dp = (__half2*)(dst + (size_t)i * 4);
        dp[0] = __floats2half2_rn(v.x, v.y);
        dp[1] = __floats2half2_rn(v.z, v.w);
    }
}

// convert + pack a [R x C] fp32 weight into fp16 dst with row stride ldd at column off
__global__ __launch_bounds__(256) void cvt_pack_kernel(const float* __restrict__ src,
                                                       f16* __restrict__ dst,
                                                       int c4, int n4, int ldd, int off) {
    int i = blockIdx.x * 256 + threadIdx.x;
    if (i < n4) {
        float4 v = *(const float4*)(src + (size_t)i * 4);
        int row = i / c4;
        int col = (i - row * c4) * 4;
        __half2* dp = (__half2*)(dst + (size_t)row * ldd + off + col);
        dp[0] = __floats2half2_rn(v.x, v.y);
        dp[1] = __floats2half2_rn(v.z, v.w);
    }
}

// pack QKV bias: [bq | 0 | bv] (fp32)
__global__ __launch_bounds__(256) void pack_bias_kernel(const float* __restrict__ bq,
                                                        const float* __restrict__ bv,
                                                        float* __restrict__ dst) {
    int i = blockIdx.x * 256 + threadIdx.x;
    if (i < D3) {
        float v = 0.f;
        if (i < DMODEL) v = bq[i];
        else if (i >= 2 * DMODEL) v = bv[i - 2 * DMODEL];
        dst[i] = v;
    }
}

// ---------------------------------------------------------------------------
// LayerNorm -> fp16 output
// ---------------------------------------------------------------------------
__global__ __launch_bounds__(256) void ln_kernel(const float* __restrict__ x,
                                                 const float* __restrict__ gam,
                                                 const float* __restrict__ bet,
                                                 f16* __restrict__ outp) {
    int r = blockIdx.x;
    const float* xr = x + (size_t)r * DMODEL;
    f16* outr = outp + (size_t)r * DMODEL;
    int tid = threadIdx.x;

    float s = 0.f, s2 = 0.f;
    for (int i = tid; i < DMODEL; i += 256) {
        float v = xr[i];
        s += v;
        s2 += v * v;
    }
    for (int off = 16; off > 0; off >>= 1) {
        s  += __shfl_xor_sync(0xffffffff, s, off);
        s2 += __shfl_xor_sync(0xffffffff, s2, off);
    }
    __shared__ float ss[8];
    __shared__ float ss2[8];
    int wid = tid >> 5;
    int lane = tid & 31;
    if (lane == 0) { ss[wid] = s; ss2[wid] = s2; }
    __syncthreads();
    if (wid == 0) {
        s  = (lane < 8) ? ss[lane]  : 0.f;
        s2 = (lane < 8) ? ss2[lane] : 0.f;
        for (int off = 4; off > 0; off >>= 1) {
            s  += __shfl_xor_sync(0xffffffff, s, off);
            s2 += __shfl_xor_sync(0xffffffff, s2, off);
        }
        if (lane == 0) { ss[0] = s; ss2[0] = s2; }
    }
    __syncthreads();
    float mu = ss[0] * (1.0f / DMODEL);
    float var = ss2[0] * (1.0f / DMODEL) - mu * mu;
    float inv = rsqrtf(var + LN_EPS);
    for (int i = tid; i < DMODEL; i += 256) {
        float v = (xr[i] - mu) * inv * gam[i] + bet[i];
        outr[i] = __float2half_rn(v);
    }
}

// ---------------------------------------------------------------------------
// fp16 tensor-core GEMM: C[M,N] = A[M,K] @ B[K,N] (+bias)(+gelu|+res)
// BM=128 BN=128 BK=32, 8 warps (4x2), warp tile 32x64, m16n8k16 f16 mma.
// OUTMODE: 0 = fp32, 1 = fp32 tf32-rounded, 2 = fp16
// ---------------------------------------------------------------------------
#define EPI_BIAS 0
#define EPI_GELU 1
#define EPI_RES  2

#define APITCH 40
#define BPITCH 136

__device__ __forceinline__ void ldsm_x4(u32& r0, u32& r1, u32& r2, u32& r3, u32 addr) {
    asm volatile("ldmatrix.sync.aligned.m8n8.x4.shared.b16 {%0,%1,%2,%3},[%4];\n"
                 : "=r"(r0), "=r"(r1), "=r"(r2), "=r"(r3) : "r"(addr));
}
__device__ __forceinline__ void ldsm_x4_t(u32& r0, u32& r1, u32& r2, u32& r3, u32 addr) {
    asm volatile("ldmatrix.sync.aligned.m8n8.x4.trans.shared.b16 {%0,%1,%2,%3},[%4];\n"
                 : "=r"(r0), "=r"(r1), "=r"(r2), "=r"(r3) : "r"(addr));
}
__device__ __forceinline__ void mma_f16(float* c, const u32* a, u32 b0, u32 b1) {
    asm volatile(
        "mma.sync.aligned.m16n8k16.row.col.f32.f16.f16.f32 "
        "{%0,%1,%2,%3},{%4,%5,%6,%7},{%8,%9},{%0,%1,%2,%3};\n"
        : "+f"(c[0]), "+f"(c[1]), "+f"(c[2]), "+f"(c[3])
        : "r"(a[0]), "r"(a[1]), "r"(a[2]), "r"(a[3]), "r"(b0), "r"(b1));
}
__device__ __forceinline__ void cp_async16(u32 dst, const void* src) {
    asm volatile("cp.async.cg.shared.global [%0],[%1],16;\n" :: "r"(dst), "l"(src));
}
__device__ __forceinline__ void cp_commit() {
    asm volatile("cp.async.commit_group;\n");
}
__device__ __forceinline__ void cp_wait1() {
    asm volatile("cp.async.wait_group 1;\n");
}
__device__ __forceinline__ void cp_wait0() {
    asm volatile("cp.async.wait_group 0;\n");
}

__device__ __forceinline__ void hg_load_tile(
    const f16* A, const f16* B, f16* As_s, f16* Bs_s,
    int k0, int bm, int bn, int K, int N,
    int a_ld_row, int a_ld_col, int b_ld_row, int b_ld_col) {
    u32 d0 = (u32)__cvta_generic_to_shared(As_s + a_ld_row * APITCH + a_ld_col);
    cp_async16(d0, A + (size_t)(bm * 128 + a_ld_row) * K + k0 + a_ld_col);
    u32 d1 = (u32)__cvta_generic_to_shared(As_s + (a_ld_row + 64) * APITCH + a_ld_col);
    cp_async16(d1, A + (size_t)(bm * 128 + a_ld_row + 64) * K + k0 + a_ld_col);
    u32 d2 = (u32)__cvta_generic_to_shared(Bs_s + b_ld_row * BPITCH + b_ld_col);
    cp_async16(d2, B + (size_t)(k0 + b_ld_row) * N + bn * 128 + b_ld_col);
    u32 d3 = (u32)__cvta_generic_to_shared(Bs_s + (b_ld_row + 16) * BPITCH + b_ld_col);
    cp_async16(d3, B + (size_t)(k0 + b_ld_row + 16) * N + bn * 128 + b_ld_col);
}

template <int EPI, int OUTMODE>
__global__ __launch_bounds__(256) void hgemm_kernel(
    const f16* __restrict__ A, const f16* __restrict__ B,
    const float* __restrict__ bias, const float* __restrict__ res,
    void* __restrict__ Cout, int M, int N, int K) {
    __shared__ f16 As[2 * 128 * APITCH];
    __shared__ f16 Bs[2 * 32 * BPITCH];

    int tid = threadIdx.x;
    int bm = blockIdx.y;
    int bn = blockIdx.x;
    int lane = tid & 31;
    int warp = tid >> 5;
    int wm = warp >> 1;
    int wn = warp & 1;

    int a_ld_row = tid >> 2;        // 0..63
    int a_ld_col = (tid & 3) * 8;
    int b_ld_row = tid >> 4;        // 0..15
    int b_ld_col = (tid & 15) * 8;

    float acc[2][8][4];
#pragma unroll
    for (int mi = 0; mi < 2; mi++) {
#pragma unroll
        for (int nj = 0; nj < 8; nj++) {
#pragma unroll
            for (int e = 0; e < 4; e++) acc[mi][nj][e] = 0.f;
        }
    }

    int KT = K / 32;

    hg_load_tile(A, B, As, Bs, 0, bm, bn, K, N,
                 a_ld_row, a_ld_col, b_ld_row, b_ld_col);
    cp_commit();

    int a_row = wm * 32 + (lane & 15);
    int a_csel = (lane >> 4) * 8;
    int b_row = (lane & 15);
    int b_csel = wn * 64 + (lane >> 4) * 8;

    for (int kt = 0; kt < KT; kt++) {
        int s = kt & 1;
        if (kt + 1 < KT) {
            int s2 = s ^ 1;
            hg_load_tile(A, B, As + s2 * 128 * APITCH, Bs + s2 * 32 * BPITCH,
                         (kt + 1) * 32, bm, bn, K, N,
                         a_ld_row, a_ld_col, b_ld_row, b_ld_col);
            cp_commit();
            cp_wait1();
        } else {
            cp_wait0();
        }
        __syncthreads();

        f16* As_s = As + s * 128 * APITCH;
        f16* Bs_s = Bs + s * 32 * BPITCH;

#pragma unroll
        for (int kk = 0; kk < 2; kk++) {
            u32 a_frag[2][4];
            u32 b_frag[4][4];
#pragma unroll
            for (int mi = 0; mi < 2; mi++) {
                u32 addr = (u32)__cvta_generic_to_shared(
                    As_s + (a_row + mi * 16) * APITCH + kk * 16 + a_csel);
                ldsm_x4(a_frag[mi][0], a_frag[mi][1], a_frag[mi][2], a_frag[mi][3], addr);
            }
#pragma unroll
            for (int nj = 0; nj < 4; nj++) {
                u32 addr = (u32)__cvta_generic_to_shared(
                    Bs_s + (kk * 16 + b_row) * BPITCH + nj * 16 + b_csel);
                ldsm_x4_t(b_frag[nj][0], b_frag[nj][1], b_frag[nj][2], b_frag[nj][3], addr);
            }
#pragma unroll
            for (int mi = 0; mi < 2; mi++) {
#pragma unroll
                for (int nj = 0; nj < 4; nj++) {
                    mma_f16(acc[mi][2 * nj],     a_frag[mi], b_frag[nj][0], b_frag[nj][1]);
                    mma_f16(acc[mi][2 * nj + 1], a_frag[mi], b_frag[nj][2], b_frag[nj][3]);
                }
            }
        }
        __syncthreads();
    }

    // ---- epilogue ----
    int gID = lane >> 2;
    int tig = lane & 3;
#pragma unroll
    for (int mi = 0; mi < 2; mi++) {
        int row0 = bm * 128 + wm * 32 + mi * 16 + gID;
#pragma unroll
        for (int nj = 0; nj < 8; nj++) {
            int col = bn * 128 + wn * 64 + nj * 8 + tig * 2;
            float v0 = acc[mi][nj][0];
            float v1 = acc[mi][nj][1];
            float v2 = acc[mi][nj][2];
            float v3 = acc[mi][nj][3];
            if (bias != 0) {
                float b0 = bias[col];
                float b1 = bias[col + 1];
                v0 += b0; v1 += b1; v2 += b0; v3 += b1;
            }
            if (EPI == EPI_GELU) {
                v0 = 0.5f * v0 * (1.0f + erff(v0 * 0.70710678118654752f));
                v1 = 0.5f * v1 * (1.0f + erff(v1 * 0.70710678118654752f));
                v2 = 0.5f * v2 * (1.0f + erff(v2 * 0.70710678118654752f));
                v3 = 0.5f * v3 * (1.0f + erff(v3 * 0.70710678118654752f));
            }
            if (EPI == EPI_RES) {
                v0 += res[(size_t)row0 * N + col];
                v1 += res[(size_t)row0 * N + col + 1];
                v2 += res[(size_t)(row0 + 8) * N + col];
                v3 += res[(size_t)(row0 + 8) * N + col + 1];
            }
            if (OUTMODE == 2) {
                f16* C = (f16*)Cout;
                *(__half2*)(C + (size_t)row0 * N + col) = __floats2half2_rn(v0, v1);
                *(__half2*)(C + (size_t)(row0 + 8) * N + col) = __floats2half2_rn(v2, v3);
            } else {
                if (OUTMODE == 1) {
                    v0 = to_tf32(v0);
                    v1 = to_tf32(v1);
                    v2 = to_tf32(v2);
                    v3 = to_tf32(v3);
                }
                float* C = (float*)Cout;
                C[(size_t)row0 * N + col] = v0;
                C[(size_t)row0 * N + col + 1] = v1;
                C[(size_t)(row0 + 8) * N + col] = v2;
                C[(size_t)(row0 + 8) * N + col + 1] = v3;
            }
        }
    }
}

// ---------------------------------------------------------------------------
// Block-diagonal attention, tensor-core tf32. q/k/v fp32 (tf32-rounded),
// row stride ldqkv; output fp16.
// ---------------------------------------------------------------------------
#define SPITCH 516
#define QPITCH 68
#define KVPITCH_K 73
#define KVPITCH_V 72
#define ATT_SMEM_FLOATS (64 * SPITCH + 64 * QPITCH + 64 * KVPITCH_K)

__device__ __forceinline__ void mma_tf32(float* c, u32 a0, u32 a1, u32 a2, u32 a3,
                                         u32 b0, u32 b1) {
    asm volatile(
        "mma.sync.aligned.m16n8k8.row.col.f32.tf32.tf32.f32 "
        "{%0,%1,%2,%3},{%4,%5,%6,%7},{%8,%9},{%0,%1,%2,%3};\n"
        : "+f"(c[0]), "+f"(c[1]), "+f"(c[2]), "+f"(c[3])
        : "r"(a0), "r"(a1), "r"(a2), "r"(a3), "r"(b0), "r"(b1));
}

__global__ __launch_bounds__(256) void attn_kernel(
    const float* __restrict__ q, const float* __restrict__ k,
    const float* __restrict__ v, const int* __restrict__ cu,
    f16* __restrict__ outp, int ldqkv) {
    extern __shared__ float sm[];
    float* sc  = sm;
    float* Qs  = sm + 64 * SPITCH;
    float* KVs = Qs + 64 * QPITCH;

    int h = blockIdx.y;
    int q0 = blockIdx.x * 64;

    int g = 0;
    for (int i = 0; i < NSEG; i++) {
        if (cu[i] <= q0) g = i;
    }
    int s0 = cu[g];
    int s1 = cu[g + 1];
    int len = s1 - s0;
    if (len > 512) len = 512;
    int nchunks = (len + 63) >> 6;

    int tid = threadIdx.x;
    int lane = tid & 31;
    int warp = tid >> 5;
    int wm = warp >> 1;
    int wn = warp & 1;
    int gID = lane >> 2;
    int tig = lane & 3;
    const float scale = 0.125f;

#pragma unroll
    for (int t = 0; t < 4; t++) {
        int gi = tid + t * 256;
        int i = gi >> 4;
        int d4 = (gi & 15) * 4;
        float4 qv = *(const float4*)(q + (size_t)(q0 + i) * ldqkv + h * HDIM + d4);
        *(float4*)(Qs + i * QPITCH + d4) = qv;
    }
    __syncthreads();

    int m0 = wm * 16;
    u32 qa[8][4];
#pragma unroll
    for (int ks = 0; ks < 8; ks++) {
        int k0 = ks * 8;
        qa[ks][0] = __float_as_uint(Qs[(m0 + gID) * QPITCH + k0 + tig]);
        qa[ks][1] = __float_as_uint(Qs[(m0 + 8 + gID) * QPITCH + k0 + tig]);
        qa[ks][2] = __float_as_uint(Qs[(m0 + gID) * QPITCH + k0 + 4 + tig]);
        qa[ks][3] = __float_as_uint(Qs[(m0 + 8 + gID) * QPITCH + k0 + 4 + tig]);
    }

    for (int c = 0; c < nchunks; c++) {
        __syncthreads();
#pragma unroll
        for (int t = 0; t < 4; t++) {
            int gi = tid + t * 256;
            int j = gi >> 4;
            int d4 = (gi & 15) * 4;
            int krow = s0 + c * 64 + j;
            float4 kv = make_float4(0.f, 0.f, 0.f, 0.f);
            if (krow < s1) {
                kv = *(const float4*)(k + (size_t)krow * ldqkv + h * HDIM + d4);
            }
            KVs[(d4 + 0) * KVPITCH_K + j] = kv.x;
            KVs[(d4 + 1) * KVPITCH_K + j] = kv.y;
            KVs[(d4 + 2) * KVPITCH_K + j] = kv.z;
            KVs[(d4 + 3) * KVPITCH_K + j] = kv.w;
        }
        __syncthreads();

        float acc[4][4];
#pragma unroll
        for (int nt = 0; nt < 4; nt++) {
#pragma unroll
            for (int e = 0; e < 4; e++) acc[nt][e] = 0.f;
        }
#pragma unroll
        for (int ks = 0; ks < 8; ks++) {
            int k0 = ks * 8;
#pragma unroll
            for (int nt = 0; nt < 4; nt++) {
                int n0 = wn * 32 + nt * 8;
                u32 b0 = __float_as_uint(KVs[(k0 + tig) * KVPITCH_K + n0 + gID]);
                u32 b1 = __float_as_uint(KVs[(k0 + 4 + tig) * KVPITCH_K + n0 + gID]);
                mma_tf32(acc[nt], qa[ks][0], qa[ks][1], qa[ks][2], qa[ks][3], b0, b1);
            }
        }
        int row0 = m0 + gID;
#pragma unroll
        for (int nt = 0; nt < 4; nt++) {
            int col = c * 64 + wn * 32 + nt * 8 + tig * 2;
            sc[row0 * SPITCH + col]           = acc[nt][0] * scale;
            sc[row0 * SPITCH + col + 1]       = acc[nt][1] * scale;
            sc[(row0 + 8) * SPITCH + col]     = acc[nt][2] * scale;
            sc[(row0 + 8) * SPITCH + col + 1] = acc[nt][3] * scale;
        }
    }
    __syncthreads();

    for (int r = warp; r < 64; r += 8) {
        float* row = sc + r * SPITCH;
        float m = -FLT_MAX;
        for (int j = lane; j < len; j += 32) m = fmaxf(m, row[j]);
        for (int off = 16; off > 0; off >>= 1) {
            m = fmaxf(m, __shfl_xor_sync(0xffffffff, m, off));
        }
        float s = 0.f;
        for (int j = lane; j < len; j += 32) {
            float e = __expf(row[j] - m);
            row[j] = e;
            s += e;
        }
        for (int off = 16; off > 0; off >>= 1) {
            s += __shfl_xor_sync(0xffffffff, s, off);
        }
        float inv = 1.0f / s;
        for (int j = lane; j < len; j += 32) row[j] = to_tf32(row[j] * inv);
    }
    __syncthreads();

    float acco[4][4];
#pragma unroll
    for (int nt = 0; nt < 4; nt++) {
#pragma unroll
        for (int e = 0; e < 4; e++) acco[nt][e] = 0.f;
    }

    for (int c = 0; c < nchunks; c++) {
        __syncthreads();
#pragma unroll
        for (int t = 0; t < 4; t++) {
            int gi = tid + t * 256;
            int j = gi >> 4;
            int d4 = (gi & 15) * 4;
            int vrow = s0 + c * 64 + j;
            float4 vv = make_float4(0.f, 0.f, 0.f, 0.f);
            if (vrow < s1) {
                vv = *(const float4*)(v + (size_t)vrow * ldqkv + h * HDIM + d4);
            }
            *(float4*)(KVs + j * KVPITCH_V + d4) = vv;
        }
        __syncthreads();

#pragma unroll
        for (int ks = 0; ks < 8; ks++) {
            int kg = c * 64 + ks * 8;
            int kl = ks * 8;
            u32 pa0 = __float_as_uint(sc[(m0 + gID) * SPITCH + kg + tig]);
            u32 pa1 = __float_as_uint(sc[(m0 + 8 + gID) * SPITCH + kg + tig]);
            u32 pa2 = __float_as_uint(sc[(m0 + gID) * SPITCH + kg + 4 + tig]);
            u32 pa3 = __float_as_uint(sc[(m0 + 8 + gID) * SPITCH + kg + 4 + tig]);
#pragma unroll
            for (int nt = 0; nt < 4; nt++) {
                int n0 = wn * 32 + nt * 8;
                u32 b0 = __float_as_uint(KVs[(kl + tig) * KVPITCH_V + n0 + gID]);
                u32 b1 = __float_as_uint(KVs[(kl + 4 + tig) * KVPITCH_V + n0 + gID]);
                mma_tf32(acco[nt], pa0, pa1, pa2, pa3, b0, b1);
            }
        }
    }

    int orow0 = q0 + m0 + gID;
#pragma unroll
    for (int nt = 0; nt < 4; nt++) {
        int col = h * HDIM + wn * 32 + nt * 8 + tig * 2;
        *(__half2*)(outp + (size_t)orow0 * DMODEL + col) =
            __floats2half2_rn(acco[nt][0], acco[nt][1]);
        *(__half2*)(outp + (size_t)(orow0 + 8) * DMODEL + col) =
            __floats2half2_rn(acco[nt][2], acco[nt][3]);
    }
}

// ---------------------------------------------------------------------------
// launch
// ---------------------------------------------------------------------------
extern "C" void kernel_launch(void* const* d_in, const int* in_sizes, int n_in,
                              void* d_out, int out_size) {
    const float* hidden = (const float*)d_in[0];
    const int*   cu     = (const int*)d_in[1];
    const float* Wq = (const float*)d_in[2];
    const float* bq = (const float*)d_in[3];
    const float* Wk = (const float*)d_in[4];
    const float* Wv = (const float*)d_in[5];
    const float* bv = (const float*)d_in[6];
    const float* Wo = (const float*)d_in[7];
    const float* bo = (const float*)d_in[8];
    const float* ln1_g = (const float*)d_in[9];
    const float* ln1_b = (const float*)d_in[10];
    const float* Wf1 = (const float*)d_in[11];
    const float* bf1 = (const float*)d_in[12];
    const float* Wf2 = (const float*)d_in[13];
    const float* bf2 = (const float*)d_in[14];
    const float* ln2_g = (const float*)d_in[15];
    const float* ln2_b = (const float*)d_in[16];
    float* out = (float*)d_out;

    float *qkvp, *hp, *bqkvp;
    f16 *xlnp, *attnp, *ylnp, *ffnp, *wqkvp, *wop, *wf1p, *wf2p;
    cudaGetSymbolAddress((void**)&qkvp,  g_qkv);
    cudaGetSymbolAddress((void**)&hp,    g_h);
    cudaGetSymbolAddress((void**)&bqkvp, g_bqkv);
    cudaGetSymbolAddress((void**)&xlnp,  g_xln);
    cudaGetSymbolAddress((void**)&attnp, g_attn);
    cudaGetSymbolAddress((void**)&ylnp,  g_yln);
    cudaGetSymbolAddress((void**)&ffnp,  g_ffn);
    cudaGetSymbolAddress((void**)&wqkvp, g_wqkv);
    cudaGetSymbolAddress((void**)&wop,   g_wo);
    cudaGetSymbolAddress((void**)&wf1p,  g_wf1);
    cudaGetSymbolAddress((void**)&wf2p,  g_wf2);

    static bool attr_set = false;
    if (!attr_set) {
        cudaFuncSetAttribute(attn_kernel, cudaFuncAttributeMaxDynamicSharedMemorySize,
                             ATT_SMEM_FLOATS * (int)sizeof(float));
        attr_set = true;
    }

    dim3 blk(256);
    int nDD4 = DMODEL * DMODEL / 4;
    int nDF4 = DMODEL * FFN / 4;
    int c4 = DMODEL / 4;
    cvt_pack_kernel<<<(nDD4 + 255) / 256, blk>>>(Wq, wqkvp, c4, nDD4, D3, 0);
    cvt_pack_kernel<<<(nDD4 + 255) / 256, blk>>>(Wk, wqkvp, c4, nDD4, D3, DMODEL);
    cvt_pack_kernel<<<(nDD4 + 255) / 256, blk>>>(Wv, wqkvp, c4, nDD4, D3, 2 * DMODEL);
    pack_bias_kernel<<<(D3 + 255) / 256, blk>>>(bq, bv, bqkvp);
    cvt_kernel<<<(nDD4 + 255) / 256, blk>>>(Wo,  wop,  nDD4);
    cvt_kernel<<<(nDF4 + 255) / 256, blk>>>(Wf1, wf1p, nDF4);
    cvt_kernel<<<(nDF4 + 255) / 256, blk>>>(Wf2, wf2p, nDF4);

    dim3 gemmQKV(D3 / 128, SEQ / 128);
    dim3 gemmDD(DMODEL / 128, SEQ / 128);
    dim3 gemmDF(FFN / 128, SEQ / 128);

    ln_kernel<<<SEQ, blk>>>(hidden, ln1_g, ln1_b, xlnp);
    // fused QKV: fp16 mma, outputs tf32-rounded fp32 for attention
    hgemm_kernel<EPI_BIAS, 1><<<gemmQKV, blk>>>(
        xlnp, wqkvp, bqkvp, 0, qkvp, SEQ, D3, DMODEL);
    attn_kernel<<<dim3(SEQ / 64, NHEAD), blk, ATT_SMEM_FLOATS * sizeof(float)>>>(
        qkvp, qkvp + DMODEL, qkvp + 2 * DMODEL, cu, attnp, D3);
    hgemm_kernel<EPI_RES, 0><<<gemmDD, blk>>>(
        attnp, wop, bo, hidden, hp, SEQ, DMODEL, DMODEL);
    ln_kernel<<<SEQ, blk>>>(hp, ln2_g, ln2_b, ylnp);
    hgemm_kernel<EPI_GELU, 2><<<gemmDF, blk>>>(
        ylnp, wf1p, bf1, 0, ffnp, SEQ, FFN, DMODEL);
    hgemm_kernel<EPI_RES, 0><<<gemmDD, blk>>>(
        ffnp, wf2p, bf2, hp, out, SEQ, DMODEL, FFN);
}

// round 10
// speedup vs baseline: 1.8933x; 1.0818x over previous
#include <cuda_runtime.h>
#include <cuda_fp16.h>
#include <cstdint>
#include <math.h>
#include <float.h>

#define SEQ 4096
#define DMODEL 1280
#define NHEAD 20
#define HDIM 64
#define FFN 5120
#define NSEG 8
#define LN_EPS 1e-5f
#define D3 (3 * DMODEL)

typedef unsigned int u32;
typedef __half f16;

// ---------------------------------------------------------------------------
// Scratch (device globals; no runtime allocation allowed)
// ---------------------------------------------------------------------------
__device__ f16   g_qkv[SEQ * D3];
__device__ float g_h[SEQ * DMODEL];
__device__ f16   g_xln[SEQ * DMODEL];
__device__ f16   g_attn[SEQ * DMODEL];
__device__ f16   g_yln[SEQ * DMODEL];
__device__ f16   g_ffn[SEQ * FFN];
__device__ f16   g_wqkv[DMODEL * D3];
__device__ float g_bqkv[D3];
__device__ f16   g_wo[DMODEL * DMODEL];
__device__ f16   g_wf1[DMODEL * FFN];
__device__ f16   g_wf2[FFN * DMODEL];

// ---------------------------------------------------------------------------
// fp32 -> fp16 convert (float4 granularity)
// ---------------------------------------------------------------------------
__global__ __launch_bounds__(256) void cvt_kernel(const float* __restrict__ src,
                                                  f16* __restrict__ dst, int n4) {
    int i = blockIdx.x * 256 + threadIdx.x;
    if (i < n4) {
        float4 v = *(const float4*)(src + (size_t)i * 4);
        __half2* dp = (__half2*)(dst + (size_t)i * 4);
        dp[0] = __floats2half2_rn(v.x, v.y);
        dp[1] = __floats2half2_rn(v.z, v.w);
    }
}

// convert + pack a [R x C] fp32 weight into fp16 dst with row stride ldd at column off
__global__ __launch_bounds__(256) void cvt_pack_kernel(const float* __restrict__ src,
                                                       f16* __restrict__ dst,
                                                       int c4, int n4, int ldd, int off) {
    int i = blockIdx.x * 256 + threadIdx.x;
    if (i < n4) {
        float4 v = *(const float4*)(src + (size_t)i * 4);
        int row = i / c4;
        int col = (i - row * c4) * 4;
        __half2* dp = (__half2*)(dst + (size_t)row * ldd + off + col);
        dp[0] = __floats2half2_rn(v.x, v.y);
        dp[1] = __floats2half2_rn(v.z, v.w);
    }
}

// pack QKV bias: [bq | 0 | bv] (fp32)
__global__ __launch_bounds__(256) void pack_bias_kernel(const float* __restrict__ bq,
                                                        const float* __restrict__ bv,
                                                        float* __restrict__ dst) {
    int i = blockIdx.x * 256 + threadIdx.x;
    if (i < D3) {
        float v = 0.f;
        if (i < DMODEL) v = bq[i];
        else if (i >= 2 * DMODEL) v = bv[i - 2 * DMODEL];
        dst[i] = v;
    }
}

// ---------------------------------------------------------------------------
// LayerNorm -> fp16 output
// ---------------------------------------------------------------------------
__global__ __launch_bounds__(256) void ln_kernel(const float* __restrict__ x,
                                                 const float* __restrict__ gam,
                                                 const float* __restrict__ bet,
                                                 f16* __restrict__ outp) {
    int r = blockIdx.x;
    const float* xr = x + (size_t)r * DMODEL;
    f16* outr = outp + (size_t)r * DMODEL;
    int tid = threadIdx.x;

    float s = 0.f, s2 = 0.f;
    for (int i = tid; i < DMODEL; i += 256) {
        float v = xr[i];
        s += v;
        s2 += v * v;
    }
    for (int off = 16; off > 0; off >>= 1) {
        s  += __shfl_xor_sync(0xffffffff, s, off);
        s2 += __shfl_xor_sync(0xffffffff, s2, off);
    }
    __shared__ float ss[8];
    __shared__ float ss2[8];
    int wid = tid >> 5;
    int lane = tid & 31;
    if (lane == 0) { ss[wid] = s; ss2[wid] = s2; }
    __syncthreads();
    if (wid == 0) {
        s  = (lane < 8) ? ss[lane]  : 0.f;
        s2 = (lane < 8) ? ss2[lane] : 0.f;
        for (int off = 4; off > 0; off >>= 1) {
            s  += __shfl_xor_sync(0xffffffff, s, off);
            s2 += __shfl_xor_sync(0xffffffff, s2, off);
        }
        if (lane == 0) { ss[0] = s; ss2[0] = s2; }
    }
    __syncthreads();
    float mu = ss[0] * (1.0f / DMODEL);
    float var = ss2[0] * (1.0f / DMODEL) - mu * mu;
    float inv = rsqrtf(var + LN_EPS);
    for (int i = tid; i < DMODEL; i += 256) {
        float v = (xr[i] - mu) * inv * gam[i] + bet[i];
        outr[i] = __float2half_rn(v);
    }
}

// ---------------------------------------------------------------------------
// fp16 tensor-core GEMM: C[M,N] = A[M,K] @ B[K,N] (+bias)(+gelu|+res)
// BM=128 BN=128 BK=32, 8 warps (4x2), warp tile 32x64, m16n8k16 f16 mma.
// OUTMODE: 0 = fp32, 2 = fp16
// ---------------------------------------------------------------------------
#define EPI_BIAS 0
#define EPI_GELU 1
#define EPI_RES  2

#define APITCH 40
#define BPITCH 136

__device__ __forceinline__ void ldsm_x4(u32& r0, u32& r1, u32& r2, u32& r3, u32 addr) {
    asm volatile("ldmatrix.sync.aligned.m8n8.x4.shared.b16 {%0,%1,%2,%3},[%4];\n"
                 : "=r"(r0), "=r"(r1), "=r"(r2), "=r"(r3) : "r"(addr));
}
__device__ __forceinline__ void ldsm_x4_t(u32& r0, u32& r1, u32& r2, u32& r3, u32 addr) {
    asm volatile("ldmatrix.sync.aligned.m8n8.x4.trans.shared.b16 {%0,%1,%2,%3},[%4];\n"
                 : "=r"(r0), "=r"(r1), "=r"(r2), "=r"(r3) : "r"(addr));
}
__device__ __forceinline__ void mma_f16(float* c, const u32* a, u32 b0, u32 b1) {
    asm volatile(
        "mma.sync.aligned.m16n8k16.row.col.f32.f16.f16.f32 "
        "{%0,%1,%2,%3},{%4,%5,%6,%7},{%8,%9},{%0,%1,%2,%3};\n"
        : "+f"(c[0]), "+f"(c[1]), "+f"(c[2]), "+f"(c[3])
        : "r"(a[0]), "r"(a[1]), "r"(a[2]), "r"(a[3]), "r"(b0), "r"(b1));
}
__device__ __forceinline__ void mma_f16_s(float* c, u32 a0, u32 a1, u32 a2, u32 a3,
                                          u32 b0, u32 b1) {
    asm volatile(
        "mma.sync.aligned.m16n8k16.row.col.f32.f16.f16.f32 "
        "{%0,%1,%2,%3},{%4,%5,%6,%7},{%8,%9},{%0,%1,%2,%3};\n"
        : "+f"(c[0]), "+f"(c[1]), "+f"(c[2]), "+f"(c[3])
        : "r"(a0), "r"(a1), "r"(a2), "r"(a3), "r"(b0), "r"(b1));
}
__device__ __forceinline__ void cp_async16(u32 dst, const void* src) {
    asm volatile("cp.async.cg.shared.global [%0],[%1],16;\n" :: "r"(dst), "l"(src));
}
__device__ __forceinline__ void cp_commit() {
    asm volatile("cp.async.commit_group;\n");
}
__device__ __forceinline__ void cp_wait1() {
    asm volatile("cp.async.wait_group 1;\n");
}
__device__ __forceinline__ void cp_wait0() {
    asm volatile("cp.async.wait_group 0;\n");
}

__device__ __forceinline__ void hg_load_tile(
    const f16* A, const f16* B, f16* As_s, f16* Bs_s,
    int k0, int bm, int bn, int K, int N,
    int a_ld_row, int a_ld_col, int b_ld_row, int b_ld_col) {
    u32 d0 = (u32)__cvta_generic_to_shared(As_s + a_ld_row * APITCH + a_ld_col);
    cp_async16(d0, A + (size_t)(bm * 128 + a_ld_row) * K + k0 + a_ld_col);
    u32 d1 = (u32)__cvta_generic_to_shared(As_s + (a_ld_row + 64) * APITCH + a_ld_col);
    cp_async16(d1, A + (size_t)(bm * 128 + a_ld_row + 64) * K + k0 + a_ld_col);
    u32 d2 = (u32)__cvta_generic_to_shared(Bs_s + b_ld_row * BPITCH + b_ld_col);
    cp_async16(d2, B + (size_t)(k0 + b_ld_row) * N + bn * 128 + b_ld_col);
    u32 d3 = (u32)__cvta_generic_to_shared(Bs_s + (b_ld_row + 16) * BPITCH + b_ld_col);
    cp_async16(d3, B + (size_t)(k0 + b_ld_row + 16) * N + bn * 128 + b_ld_col);
}

template <int EPI, int OUTMODE>
__global__ __launch_bounds__(256) void hgemm_kernel(
    const f16* __restrict__ A, const f16* __restrict__ B,
    const float* __restrict__ bias, const float* __restrict__ res,
    void* __restrict__ Cout, int M, int N, int K) {
    __shared__ f16 As[2 * 128 * APITCH];
    __shared__ f16 Bs[2 * 32 * BPITCH];

    int tid = threadIdx.x;
    int bm = blockIdx.y;
    int bn = blockIdx.x;
    int lane = tid & 31;
    int warp = tid >> 5;
    int wm = warp >> 1;
    int wn = warp & 1;

    int a_ld_row = tid >> 2;
    int a_ld_col = (tid & 3) * 8;
    int b_ld_row = tid >> 4;
    int b_ld_col = (tid & 15) * 8;

    float acc[2][8][4];
#pragma unroll
    for (int mi = 0; mi < 2; mi++) {
#pragma unroll
        for (int nj = 0; nj < 8; nj++) {
#pragma unroll
            for (int e = 0; e < 4; e++) acc[mi][nj][e] = 0.f;
        }
    }

    int KT = K / 32;

    hg_load_tile(A, B, As, Bs, 0, bm, bn, K, N,
                 a_ld_row, a_ld_col, b_ld_row, b_ld_col);
    cp_commit();

    int a_row = wm * 32 + (lane & 15);
    int a_csel = (lane >> 4) * 8;
    int b_row = (lane & 15);
    int b_csel = wn * 64 + (lane >> 4) * 8;

    for (int kt = 0; kt < KT; kt++) {
        int s = kt & 1;
        if (kt + 1 < KT) {
            int s2 = s ^ 1;
            hg_load_tile(A, B, As + s2 * 128 * APITCH, Bs + s2 * 32 * BPITCH,
                         (kt + 1) * 32, bm, bn, K, N,
                         a_ld_row, a_ld_col, b_ld_row, b_ld_col);
            cp_commit();
            cp_wait1();
        } else {
            cp_wait0();
        }
        __syncthreads();

        f16* As_s = As + s * 128 * APITCH;
        f16* Bs_s = Bs + s * 32 * BPITCH;

#pragma unroll
        for (int kk = 0; kk < 2; kk++) {
            u32 a_frag[2][4];
            u32 b_frag[4][4];
#pragma unroll
            for (int mi = 0; mi < 2; mi++) {
                u32 addr = (u32)__cvta_generic_to_shared(
                    As_s + (a_row + mi * 16) * APITCH + kk * 16 + a_csel);
                ldsm_x4(a_frag[mi][0], a_frag[mi][1], a_frag[mi][2], a_frag[mi][3], addr);
            }
#pragma unroll
            for (int nj = 0; nj < 4; nj++) {
                u32 addr = (u32)__cvta_generic_to_shared(
                    Bs_s + (kk * 16 + b_row) * BPITCH + nj * 16 + b_csel);
                ldsm_x4_t(b_frag[nj][0], b_frag[nj][1], b_frag[nj][2], b_frag[nj][3], addr);
            }
#pragma unroll
            for (int mi = 0; mi < 2; mi++) {
#pragma unroll
                for (int nj = 0; nj < 4; nj++) {
                    mma_f16(acc[mi][2 * nj],     a_frag[mi], b_frag[nj][0], b_frag[nj][1]);
                    mma_f16(acc[mi][2 * nj + 1], a_frag[mi], b_frag[nj][2], b_frag[nj][3]);
                }
            }
        }
        __syncthreads();
    }

    // ---- epilogue ----
    int gID = lane >> 2;
    int tig = lane & 3;
#pragma unroll
    for (int mi = 0; mi < 2; mi++) {
        int row0 = bm * 128 + wm * 32 + mi * 16 + gID;
#pragma unroll
        for (int nj = 0; nj < 8; nj++) {
            int col = bn * 128 + wn * 64 + nj * 8 + tig * 2;
            float v0 = acc[mi][nj][0];
            float v1 = acc[mi][nj][1];
            float v2 = acc[mi][nj][2];
            float v3 = acc[mi][nj][3];
            if (bias != 0) {
                float b0 = bias[col];
                float b1 = bias[col + 1];
                v0 += b0; v1 += b1; v2 += b0; v3 += b1;
            }
            if (EPI == EPI_GELU) {
                v0 = 0.5f * v0 * (1.0f + erff(v0 * 0.70710678118654752f));
                v1 = 0.5f * v1 * (1.0f + erff(v1 * 0.70710678118654752f));
                v2 = 0.5f * v2 * (1.0f + erff(v2 * 0.70710678118654752f));
                v3 = 0.5f * v3 * (1.0f + erff(v3 * 0.70710678118654752f));
            }
            if (EPI == EPI_RES) {
                v0 += res[(size_t)row0 * N + col];
                v1 += res[(size_t)row0 * N + col + 1];
                v2 += res[(size_t)(row0 + 8) * N + col];
                v3 += res[(size_t)(row0 + 8) * N + col + 1];
            }
            if (OUTMODE == 2) {
                f16* C = (f16*)Cout;
                *(__half2*)(C + (size_t)row0 * N + col) = __floats2half2_rn(v0, v1);
                *(__half2*)(C + (size_t)(row0 + 8) * N + col) = __floats2half2_rn(v2, v3);
            } else {
                float* C = (float*)Cout;
                C[(size_t)row0 * N + col] = v0;
                C[(size_t)row0 * N + col + 1] = v1;
                C[(size_t)(row0 + 8) * N + col] = v2;
                C[(size_t)(row0 + 8) * N + col + 1] = v3;
            }
        }
    }
}

// ---------------------------------------------------------------------------
// Block-diagonal attention, fp16 tensor-core. q/k/v fp16, row stride ldqkv.
// Block = 64 queries x 1 head. Warps 4x2.
// S = Q K^T: K natural [j][d], plain ldmatrix gives B fragments.
// softmax fp32 on sc; P -> fp16 buffer; O = P V with ldmatrix(.trans for V).
// ---------------------------------------------------------------------------
#define SPITCH 516     // fp32 score pitch (floats)
#define PPITCH 520     // fp16 P pitch (halves)
#define QKPITCH 72     // fp16 Q/K/V pitch (halves)
#define ATT_SMEM_BYTES (64 * SPITCH * 4 + 64 * PPITCH * 2 + 2 * 64 * QKPITCH * 2)

__global__ __launch_bounds__(256) void attn_kernel(
    const f16* __restrict__ q, const f16* __restrict__ k,
    const f16* __restrict__ v, const int* __restrict__ cu,
    f16* __restrict__ outp, int ldqkv) {
    extern __shared__ char smraw[];
    float* sc = (float*)smraw;
    f16* Pb  = (f16*)(smraw + 64 * SPITCH * 4);
    f16* Qs  = Pb + 64 * PPITCH;
    f16* KVs = Qs + 64 * QKPITCH;

    int h = blockIdx.y;
    int q0 = blockIdx.x * 64;

    int g = 0;
    for (int i = 0; i < NSEG; i++) {
        if (cu[i] <= q0) g = i;
    }
    int s0 = cu[g];
    int s1 = cu[g + 1];
    int len = s1 - s0;
    if (len > 512) len = 512;
    int nchunks = (len + 63) >> 6;

    int tid = threadIdx.x;
    int lane = tid & 31;
    int warp = tid >> 5;
    int wm = warp >> 1;      // 0..3 -> 16-row m tile
    int wn = warp & 1;       // 0..1 -> 32-col half
    int gID = lane >> 2;
    int tig = lane & 3;
    const float scale = 0.125f;

    // ---- load Q tile natural [i][d] fp16 (64 rows x 64 halves = 8 x 16B/row) ----
#pragma unroll
    for (int t = 0; t < 2; t++) {
        int gi = tid + t * 256;
        int i = gi >> 3;
        int c8 = (gi & 7) * 8;
        uint4 qv = *(const uint4*)(q + (size_t)(q0 + i) * ldqkv + h * HDIM + c8);
        *(uint4*)(Qs + i * QKPITCH + c8) = qv;
    }
    __syncthreads();

    // ---- Q A-fragments (m16 x k64 per warp, 4 ksteps of k16) ----
    int m0 = wm * 16;
    u32 qa[4][4];
#pragma unroll
    for (int ks = 0; ks < 4; ks++) {
        u32 addr = (u32)__cvta_generic_to_shared(
            Qs + (m0 + (lane & 15)) * QKPITCH + ks * 16 + (lane >> 4) * 8);
        ldsm_x4(qa[ks][0], qa[ks][1], qa[ks][2], qa[ks][3], addr);
    }

    // ---- Phase 1: scores ----
    for (int c = 0; c < nchunks; c++) {
        __syncthreads();
        // K chunk natural [j][d]
#pragma unroll
        for (int t = 0; t < 2; t++) {
            int gi = tid + t * 256;
            int j = gi >> 3;
            int c8 = (gi & 7) * 8;
            int krow = s0 + c * 64 + j;
            uint4 kv = make_uint4(0u, 0u, 0u, 0u);
            if (krow < s1) {
                kv = *(const uint4*)(k + (size_t)krow * ldqkv + h * HDIM + c8);
            }
            *(uint4*)(KVs + j * QKPITCH + c8) = kv;
        }
        __syncthreads();

        float acc[4][4];
#pragma unroll
        for (int nt = 0; nt < 4; nt++) {
#pragma unroll
            for (int e = 0; e < 4; e++) acc[nt][e] = 0.f;
        }
#pragma unroll
        for (int ks = 0; ks < 4; ks++) {
#pragma unroll
            for (int nt16 = 0; nt16 < 2; nt16++) {
                int j0w = wn * 32 + nt16 * 16;
                u32 r0, r1, r2, r3;
                u32 addr = (u32)__cvta_generic_to_shared(
                    KVs + (j0w + (lane & 15)) * QKPITCH + ks * 16 + (lane >> 4) * 8);
                ldsm_x4(r0, r1, r2, r3, addr);
                // non-trans on [n][k]: (r0,r2) = n0-7, (r1,r3) = n8-15
                mma_f16_s(acc[nt16 * 2],     qa[ks][0], qa[ks][1], qa[ks][2], qa[ks][3], r0, r2);
                mma_f16_s(acc[nt16 * 2 + 1], qa[ks][0], qa[ks][1], qa[ks][2], qa[ks][3], r1, r3);
            }
        }
        int row0 = m0 + gID;
#pragma unroll
        for (int nt = 0; nt < 4; nt++) {
            int col = c * 64 + wn * 32 + nt * 8 + tig * 2;
            sc[row0 * SPITCH + col]           = acc[nt][0] * scale;
            sc[row0 * SPITCH + col + 1]       = acc[nt][1] * scale;
            sc[(row0 + 8) * SPITCH + col]     = acc[nt][2] * scale;
            sc[(row0 + 8) * SPITCH + col + 1] = acc[nt][3] * scale;
        }
    }
    __syncthreads();

    // ---- Phase 2: softmax fp32, write P fp16 ----
    int padlen = nchunks * 64;
    for (int r = warp; r < 64; r += 8) {
        float* row = sc + r * SPITCH;
        f16* prow = Pb + r * PPITCH;
        float m = -FLT_MAX;
        for (int j = lane; j < len; j += 32) m = fmaxf(m, row[j]);
        for (int off = 16; off > 0; off >>= 1) {
            m = fmaxf(m, __shfl_xor_sync(0xffffffff, m, off));
        }
        float s = 0.f;
        for (int j = lane; j < len; j += 32) {
            float e = __expf(row[j] - m);
            row[j] = e;
            s += e;
        }
        for (int off = 16; off > 0; off >>= 1) {
            s += __shfl_xor_sync(0xffffffff, s, off);
        }
        float inv = 1.0f / s;
        for (int j = lane; j < len; j += 32) prow[j] = __float2half_rn(row[j] * inv);
        for (int j = len + lane; j < padlen; j += 32) prow[j] = __float2half_rn(0.f);
    }
    __syncthreads();

    // ---- Phase 3: O = P @ V ----
    float acco[4][4];
#pragma unroll
    for (int nt = 0; nt < 4; nt++) {
#pragma unroll
        for (int e = 0; e < 4; e++) acco[nt][e] = 0.f;
    }

    for (int c = 0; c < nchunks; c++) {
        __syncthreads();
        // V chunk natural [j][d]
#pragma unroll
        for (int t = 0; t < 2; t++) {
            int gi = tid + t * 256;
            int j = gi >> 3;
            int c8 = (gi & 7) * 8;
            int vrow = s0 + c * 64 + j;
            uint4 vv = make_uint4(0u, 0u, 0u, 0u);
            if (vrow < s1) {
                vv = *(const uint4*)(v + (size_t)vrow * ldqkv + h * HDIM + c8);
            }
            *(uint4*)(KVs + j * QKPITCH + c8) = vv;
        }
        __syncthreads();

#pragma unroll
        for (int ks = 0; ks < 4; ks++) {
            int kg = c * 64 + ks * 16;
            int kl = ks * 16;
            u32 pa0, pa1, pa2, pa3;
            u32 paddr = (u32)__cvta_generic_to_shared(
                Pb + (m0 + (lane & 15)) * PPITCH + kg + (lane >> 4) * 8);
            ldsm_x4(pa0, pa1, pa2, pa3, paddr);
#pragma unroll
            for (int nt16 = 0; nt16 < 2; nt16++) {
                int n0 = wn * 32 + nt16 * 16;
                u32 b0, b1, b2, b3;
                u32 vaddr = (u32)__cvta_generic_to_shared(
                    KVs + (kl + (lane & 15)) * QKPITCH + n0 + (lane >> 4) * 8);
                ldsm_x4_t(b0, b1, b2, b3, vaddr);
                mma_f16_s(acco[nt16 * 2],     pa0, pa1, pa2, pa3, b0, b1);
                mma_f16_s(acco[nt16 * 2 + 1], pa0, pa1, pa2, pa3, b2, b3);
            }
        }
    }

    // ---- epilogue: write fp16 attention output ----
    int orow0 = q0 + m0 + gID;
#pragma unroll
    for (int nt = 0; nt < 4; nt++) {
        int col = h * HDIM + wn * 32 + nt * 8 + tig * 2;
        *(__half2*)(outp + (size_t)orow0 * DMODEL + col) =
            __floats2half2_rn(acco[nt][0], acco[nt][1]);
        *(__half2*)(outp + (size_t)(orow0 + 8) * DMODEL + col) =
            __floats2half2_rn(acco[nt][2], acco[nt][3]);
    }
}

// ---------------------------------------------------------------------------
// launch
// ---------------------------------------------------------------------------
extern "C" void kernel_launch(void* const* d_in, const int* in_sizes, int n_in,
                              void* d_out, int out_size) {
    const float* hidden = (const float*)d_in[0];
    const int*   cu     = (const int*)d_in[1];
    const float* Wq = (const float*)d_in[2];
    const float* bq = (const float*)d_in[3];
    const float* Wk = (const float*)d_in[4];
    const float* Wv = (const float*)d_in[5];
    const float* bv = (const float*)d_in[6];
    const float* Wo = (const float*)d_in[7];
    const float* bo = (const float*)d_in[8];
    const float* ln1_g = (const float*)d_in[9];
    const float* ln1_b = (const float*)d_in[10];
    const float* Wf1 = (const float*)d_in[11];
    const float* bf1 = (const float*)d_in[12];
    const float* Wf2 = (const float*)d_in[13];
    const float* bf2 = (const float*)d_in[14];
    const float* ln2_g = (const float*)d_in[15];
    const float* ln2_b = (const float*)d_in[16];
    float* out = (float*)d_out;

    float *hp, *bqkvp;
    f16 *qkvp, *xlnp, *attnp, *ylnp, *ffnp, *wqkvp, *wop, *wf1p, *wf2p;
    cudaGetSymbolAddress((void**)&qkvp,  g_qkv);
    cudaGetSymbolAddress((void**)&hp,    g_h);
    cudaGetSymbolAddress((void**)&bqkvp, g_bqkv);
    cudaGetSymbolAddress((void**)&xlnp,  g_xln);
    cudaGetSymbolAddress((void**)&attnp, g_attn);
    cudaGetSymbolAddress((void**)&ylnp,  g_yln);
    cudaGetSymbolAddress((void**)&ffnp,  g_ffn);
    cudaGetSymbolAddress((void**)&wqkvp, g_wqkv);
    cudaGetSymbolAddress((void**)&wop,   g_wo);
    cudaGetSymbolAddress((void**)&wf1p,  g_wf1);
    cudaGetSymbolAddress((void**)&wf2p,  g_wf2);

    static bool attr_set = false;
    if (!attr_set) {
        cudaFuncSetAttribute(attn_kernel, cudaFuncAttributeMaxDynamicSharedMemorySize,
                             ATT_SMEM_BYTES);
        attr_set = true;
    }

    dim3 blk(256);
    int nDD4 = DMODEL * DMODEL / 4;
    int nDF4 = DMODEL * FFN / 4;
    int c4 = DMODEL / 4;
    cvt_pack_kernel<<<(nDD4 + 255) / 256, blk>>>(Wq, wqkvp, c4, nDD4, D3, 0);
    cvt_pack_kernel<<<(nDD4 + 255) / 256, blk>>>(Wk, wqkvp, c4, nDD4, D3, DMODEL);
    cvt_pack_kernel<<<(nDD4 + 255) / 256, blk>>>(Wv, wqkvp, c4, nDD4, D3, 2 * DMODEL);
    pack_bias_kernel<<<(D3 + 255) / 256, blk>>>(bq, bv, bqkvp);
    cvt_kernel<<<(nDD4 + 255) / 256, blk>>>(Wo,  wop,  nDD4);
    cvt_kernel<<<(nDF4 + 255) / 256, blk>>>(Wf1, wf1p, nDF4);
    cvt_kernel<<<(nDF4 + 255) / 256, blk>>>(Wf2, wf2p, nDF4);

    dim3 gemmQKV(D3 / 128, SEQ / 128);
    dim3 gemmDD(DMODEL / 128, SEQ / 128);
    dim3 gemmDF(FFN / 128, SEQ / 128);

    ln_kernel<<<SEQ, blk>>>(hidden, ln1_g, ln1_b, xlnp);
    // fused QKV: fp16 mma, fp16 outputs (attention operands)
    hgemm_kernel<EPI_BIAS, 2><<<gemmQKV, blk>>>(
        xlnp, wqkvp, bqkvp, 0, qkvp, SEQ, D3, DMODEL);
    attn_kernel<<<dim3(SEQ / 64, NHEAD), blk, ATT_SMEM_BYTES>>>(
        qkvp, qkvp + DMODEL, qkvp + 2 * DMODEL, cu, attnp, D3);
    hgemm_kernel<EPI_RES, 0><<<gemmDD, blk>>>(
        attnp, wop, bo, hidden, hp, SEQ, DMODEL, DMODEL);
    ln_kernel<<<SEQ, blk>>>(hp, ln2_g, ln2_b, ylnp);
    hgemm_kernel<EPI_GELU, 2><<<gemmDF, blk>>>(
        ylnp, wf1p, bf1, 0, ffnp, SEQ, FFN, DMODEL);
    hgemm_kernel<EPI_RES, 0><<<gemmDD, blk>>>(
        ffnp, wf2p, bf2, hp, out, SEQ, DMODEL, FFN);
}